// round 5
// baseline (speedup 1.0000x reference)
#include <cuda_runtime.h>
#include <math_constants.h>

// Outputs packed float32, reference return order:
//   [0,    N)   t_hit
//   [N,   2N)   sphere_idx (as float, -1 for miss)
//   [2N,  5N)   hit_points  (N,3)
//   [5N,  8N)   hit_normals (N,3)
//
// Decision arithmetic bit-replicates the reference fp32 op sequence in the
// half-b domain (power-of-two / sign scalings commute exactly with rn
// rounding, sqrt, div). Inner loop: 2 spheres/lane via packed f32x2 ops
// (12 packed ops/pair), groups of 4 pairs share ONE divergent-branch
// envelope via an integer sign-bit AND across the packed discriminants.

#define MAX_SPH  256
#define MAX_PAIR (MAX_SPH / 2)
#define BLOCK    256

typedef unsigned long long u64;

__device__ __forceinline__ u64 mul2(u64 a, u64 b) {
    u64 d; asm("mul.rn.f32x2 %0, %1, %2;" : "=l"(d) : "l"(a), "l"(b)); return d;
}
__device__ __forceinline__ u64 add2(u64 a, u64 b) {
    u64 d; asm("add.rn.f32x2 %0, %1, %2;" : "=l"(d) : "l"(a), "l"(b)); return d;
}
__device__ __forceinline__ u64 fma2(u64 a, u64 b, u64 c) {
    u64 d; asm("fma.rn.f32x2 %0, %1, %2, %3;" : "=l"(d) : "l"(a), "l"(b), "l"(c)); return d;
}
__device__ __forceinline__ u64 pkf(float lo, float hi) {
    return (u64)__float_as_uint(lo) | ((u64)__float_as_uint(hi) << 32);
}
__device__ __forceinline__ float lo_f(u64 v) { return __int_as_float((int)(unsigned)v); }
__device__ __forceinline__ float hi_f(u64 v) { return __int_as_float((int)(v >> 32)); }

__global__ __launch_bounds__(BLOCK)
void raysphere_kernel(const float* __restrict__ ro,
                      const float* __restrict__ rd,
                      const float* __restrict__ sc,
                      const float* __restrict__ sr,
                      float* __restrict__ out,
                      int n_rays, int n_sph)
{
    // Pre-packed pair data: sXY[k] = {pack(x0,x1), pack(y0,y1)},
    //                       sZW[k] = {pack(z0,z1), pack(w0,w1)}, w = |c|^2 - r^2
    __shared__ ulonglong2 sXY[MAX_PAIR];
    __shared__ ulonglong2 sZW[MAX_PAIR];
    __shared__ float4     s_ctr[MAX_SPH];   // for the normal gather + odd tail

    const int tid    = threadIdx.x;
    const int n_pair = n_sph >> 1;

    for (int j = tid; j < n_sph; j += BLOCK) {
        float cx = sc[3 * j + 0];
        float cy = sc[3 * j + 1];
        float cz = sc[3 * j + 2];
        float r  = sr[j];
        float s2 = __fadd_rn(__fadd_rn(__fmul_rn(cx, cx), __fmul_rn(cy, cy)),
                             __fmul_rn(cz, cz));
        float w  = __fsub_rn(s2, __fmul_rn(r, r));
        s_ctr[j] = make_float4(cx, cy, cz, w);
    }
    __syncthreads();
    for (int k = tid; k < n_pair; k += BLOCK) {
        float4 p0 = s_ctr[2 * k], p1 = s_ctr[2 * k + 1];
        sXY[k] = make_ulonglong2(pkf(p0.x, p1.x), pkf(p0.y, p1.y));
        sZW[k] = make_ulonglong2(pkf(p0.z, p1.z), pkf(p0.w, p1.w));
    }
    __syncthreads();

    const int i = blockIdx.x * BLOCK + tid;
    if (i >= n_rays) return;

    const float ox = ro[3 * i + 0];
    const float oy = ro[3 * i + 1];
    const float oz = ro[3 * i + 2];
    const float dx = rd[3 * i + 0];
    const float dy = rd[3 * i + 1];
    const float dz = rd[3 * i + 2];

    // jnp.sum(v*v): rounded squares, left-to-right add (reference order)
    const float a   = __fadd_rn(__fadd_rn(__fmul_rn(dx, dx), __fmul_rn(dy, dy)),
                                __fmul_rn(dz, dz));
    const float ddo = __fadd_rn(__fadd_rn(__fmul_rn(dx, ox), __fmul_rn(dy, oy)),
                                __fmul_rn(dz, oz));
    const float on2 = __fadd_rn(__fadd_rn(__fmul_rn(ox, ox), __fmul_rn(oy, oy)),
                                __fmul_rn(oz, oz));

    // Packed broadcast ray constants.
    // d-chain negated (exact sign flip) -> -ddc.
    // o-chain scaled by -2 (exact power-of-two*sign scale, commutes with rn
    // at every fma step) -> -2*odc bitwise, eliminating the doubling add.
    const float n2ox = __fmul_rn(-2.0f, ox);
    const float n2oy = __fmul_rn(-2.0f, oy);
    const float n2oz = __fmul_rn(-2.0f, oz);
    const u64 pndx  = pkf(-dx, -dx), pndy  = pkf(-dy, -dy), pndz  = pkf(-dz, -dz);
    const u64 pn2ox = pkf(n2ox, n2ox), pn2oy = pkf(n2oy, n2oy), pn2oz = pkf(n2oz, n2oz);
    const u64 pddo = pkf(ddo, ddo);
    const u64 pon2 = pkf(on2, on2);
    const u64 pna  = pkf(-a, -a);

    float best_m = CUDART_INF_F;   // half-b numerator reject bound
    float best_t = CUDART_INF_F;   // reference-exact t
    int   best_j = 0;

    const int n_grp4 = n_pair >> 2;     // groups of 4 pairs (8 spheres)

    for (int g = 0; g < n_grp4; g++) {
        const int kbase = g << 2;
        u64 q2v[4], x2v[4];

        #pragma unroll
        for (int u = 0; u < 4; u++) {
            const ulonglong2 A = sXY[kbase + u];   // {x0,x1},{y0,y1}
            const ulonglong2 B = sZW[kbase + u];   // {z0,z1},{w0,w1}
            const u64 nddc  = fma2(pndz,  B.x, fma2(pndy,  A.y, mul2(pndx,  A.x)));
            const u64 n2odc = fma2(pn2oz, B.x, fma2(pn2oy, A.y, mul2(pn2ox, A.x)));
            const u64 x2 = add2(pddo, nddc);              // ddo - ddc (= b/2)
            const u64 c2 = add2(add2(pon2, n2odc), B.y);  // (on2-2odc)+cconst
            q2v[u] = add2(mul2(x2, x2), mul2(pna, c2));   // disc/4 per lane
            x2v[u] = x2;
        }

        // "any of the 8 q lanes >= 0" <=> NOT all sign bits set.
        // (-0.0f cannot occur: rn cancellation yields +0.)
        const u64 qa = q2v[0] & q2v[1] & q2v[2] & q2v[3];
        const int sb = (int)((unsigned)qa & (unsigned)(qa >> 32));
        if (sb >= 0) {                                    // rare tail
            #pragma unroll
            for (int u = 0; u < 4; u++) {
                const float qlo = lo_f(q2v[u]);
                const float qhi = hi_f(q2v[u]);
                if (qlo >= 0.0f) {
                    const float x  = lo_f(x2v[u]);
                    const float sq = __fsqrt_rn(qlo);     // = sqrt_disc/2 exactly
                    const float m1 = __fsub_rn(-x, sq);
                    const float m0 = __fadd_rn(-x, sq);
                    const float m  = (m1 > 0.0f) ? m1 : m0;
                    if (m > 0.0f && m < best_m) {
                        best_m = m;
                        const float t = __fdiv_rn(m, a);  // == num/(2a) exactly
                        if (t < best_t) { best_t = t; best_j = 2 * (kbase + u); }
                    }
                }
                if (qhi >= 0.0f) {
                    const float x  = hi_f(x2v[u]);
                    const float sq = __fsqrt_rn(qhi);
                    const float m1 = __fsub_rn(-x, sq);
                    const float m0 = __fadd_rn(-x, sq);
                    const float m  = (m1 > 0.0f) ? m1 : m0;
                    if (m > 0.0f && m < best_m) {
                        best_m = m;
                        const float t = __fdiv_rn(m, a);
                        if (t < best_t) { best_t = t; best_j = 2 * (kbase + u) + 1; }
                    }
                }
            }
        }
    }

    // Leftover pairs (n_pair % 4) — per-pair test
    for (int k = n_grp4 << 2; k < n_pair; k++) {
        const ulonglong2 A = sXY[k];
        const ulonglong2 B = sZW[k];
        const u64 nddc  = fma2(pndz,  B.x, fma2(pndy,  A.y, mul2(pndx,  A.x)));
        const u64 n2odc = fma2(pn2oz, B.x, fma2(pn2oy, A.y, mul2(pn2ox, A.x)));
        const u64 x2 = add2(pddo, nddc);
        const u64 c2 = add2(add2(pon2, n2odc), B.y);
        const u64 q2 = add2(mul2(x2, x2), mul2(pna, c2));
        const int sb = (int)((unsigned)q2 & (unsigned)(q2 >> 32));
        if (sb >= 0) {
            const float qv[2] = { lo_f(q2), hi_f(q2) };
            const float xv[2] = { lo_f(x2), hi_f(x2) };
            #pragma unroll
            for (int h = 0; h < 2; h++) {
                if (qv[h] >= 0.0f) {
                    const float sq = __fsqrt_rn(qv[h]);
                    const float m1 = __fsub_rn(-xv[h], sq);
                    const float m0 = __fadd_rn(-xv[h], sq);
                    const float m  = (m1 > 0.0f) ? m1 : m0;
                    if (m > 0.0f && m < best_m) {
                        best_m = m;
                        const float t = __fdiv_rn(m, a);
                        if (t < best_t) { best_t = t; best_j = 2 * k + h; }
                    }
                }
            }
        }
    }

    // Scalar remainder if n_sph is odd
    for (int j = 2 * n_pair; j < n_sph; j++) {
        const float4 s = s_ctr[j];
        const float ddc = __fmaf_rn(dz, s.z, __fmaf_rn(dy, s.y, __fmul_rn(dx, s.x)));
        const float odc = __fmaf_rn(oz, s.z, __fmaf_rn(oy, s.y, __fmul_rn(ox, s.x)));
        const float x   = __fsub_rn(ddo, ddc);
        const float c   = __fadd_rn(__fsub_rn(on2, __fmul_rn(2.0f, odc)), s.w);
        const float q   = __fsub_rn(__fmul_rn(x, x), __fmul_rn(a, c));
        if (q >= 0.0f) {
            const float sq = __fsqrt_rn(q);
            const float m1 = __fsub_rn(-x, sq);
            const float m0 = __fadd_rn(-x, sq);
            const float m  = (m1 > 0.0f) ? m1 : m0;
            if (m > 0.0f && m < best_m) {
                best_m = m;
                const float t = __fdiv_rn(m, a);
                if (t < best_t) { best_t = t; best_j = j; }
            }
        }
    }

    const float t_hit = best_t;
    const bool  any   = isfinite(t_hit);

    const long long N = n_rays;
    out[i]     = t_hit;
    out[N + i] = any ? (float)best_j : -1.0f;

    // hit_points = o + t*d (mul then add — matches reference)
    const float hx = __fadd_rn(ox, __fmul_rn(t_hit, dx));
    const float hy = __fadd_rn(oy, __fmul_rn(t_hit, dy));
    const float hz = __fadd_rn(oz, __fmul_rn(t_hit, dz));
    out[2 * N + 3 * i + 0] = hx;
    out[2 * N + 3 * i + 1] = hy;
    out[2 * N + 3 * i + 2] = hz;

    const float4 cb = s_ctr[any ? best_j : 0];
    const float nx = __fsub_rn(hx, cb.x);
    const float ny = __fsub_rn(hy, cb.y);
    const float nz = __fsub_rn(hz, cb.z);
    const float nn = __fadd_rn(__fadd_rn(__fmul_rn(nx, nx), __fmul_rn(ny, ny)),
                               __fmul_rn(nz, nz));
    const float len = __fsqrt_rn(nn);
    out[5 * N + 3 * i + 0] = any ? __fdiv_rn(nx, len) : 0.0f;
    out[5 * N + 3 * i + 1] = any ? __fdiv_rn(ny, len) : 0.0f;
    out[5 * N + 3 * i + 2] = any ? __fdiv_rn(nz, len) : 0.0f;
}

extern "C" void kernel_launch(void* const* d_in, const int* in_sizes, int n_in,
                              void* d_out, int out_size)
{
    const float* ro = (const float*)d_in[0];   // (N,3)
    const float* rd = (const float*)d_in[1];   // (N,3)
    const float* sc = (const float*)d_in[2];   // (M,3)
    const float* sr = (const float*)d_in[3];   // (M,)

    const int n_rays = in_sizes[0] / 3;
    const int n_sph  = in_sizes[3];

    float* out = (float*)d_out;

    const int grid = (n_rays + BLOCK - 1) / BLOCK;
    raysphere_kernel<<<grid, BLOCK>>>(ro, rd, sc, sr, out, n_rays, n_sph);
}